// round 6
// baseline (speedup 1.0000x reference)
#include <cuda_runtime.h>
#include <cuda_bf16.h>
#include <cstdint>

// QuantizedEmbedding: out[i, d] = code[quant_weight[x[i], d]] * absmax[x[i] >> 2]
//   x: int32[16384]  qw: int32[50304,1024]  absmax: f32[12576]  code: f32[256]
//   out: f32[16384,1024]   (block index == v>>2 since (v%4)*1024 + d < 4096)
//
// R6: lane-private codebook. 32x replication, lane-interleaved:
//   s_code[q*32 + lane] -> bank = lane for ANY q  => zero LDS conflicts.
// Keeps R5's persistent CTAs + double-buffered group prefetch.

#define TOK 4

__global__ void __launch_bounds__(256, 4)
qembed_kernel(const int* __restrict__ x,
              const int4* __restrict__ qw,
              const float* __restrict__ absmax,
              const float* __restrict__ code,
              float4* __restrict__ out,
              int n_groups)
{
    __shared__ float s_code[256 * 32];      // 32 KB, lane-private copies
    const int t    = threadIdx.x;
    const int lane = t & 31;

    // Fill: word i -> bank i%32 = t%32, conflict-free.
    for (int i = t; i < 256 * 32; i += 256)
        s_code[i] = code[i >> 5];
    __syncthreads();

    const int G = gridDim.x;
    int g = blockIdx.x;
    if (g >= n_groups) return;

    // Prefetch first group.
    int4  q[TOK];
    float sc[TOK];
    #pragma unroll
    for (int k = 0; k < TOK; k++) {
        const int v = x[g * TOK + k];
        q[k]  = qw[(size_t)v * 256 + t];
        sc[k] = __ldg(&absmax[v >> 2]);
    }

    while (true) {
        const int gn = g + G;

        int4  qn[TOK];
        float scn[TOK];
        if (gn < n_groups) {
            // Issue next group's independent loads before processing current.
            #pragma unroll
            for (int k = 0; k < TOK; k++) {
                const int v = x[gn * TOK + k];
                qn[k]  = qw[(size_t)v * 256 + t];
                scn[k] = __ldg(&absmax[v >> 2]);
            }
        }

        // Process current group: conflict-free LDS lookups + streaming stores.
        #pragma unroll
        for (int k = 0; k < TOK; k++) {
            float4 o;
            o.x = s_code[q[k].x * 32 + lane] * sc[k];
            o.y = s_code[q[k].y * 32 + lane] * sc[k];
            o.z = s_code[q[k].z * 32 + lane] * sc[k];
            o.w = s_code[q[k].w * 32 + lane] * sc[k];
            __stcs(&out[(size_t)(g * TOK + k) * 256 + t], o);
        }

        if (gn >= n_groups) break;
        g = gn;
        #pragma unroll
        for (int k = 0; k < TOK; k++) { q[k] = qn[k]; sc[k] = scn[k]; }
    }
}

extern "C" void kernel_launch(void* const* d_in, const int* in_sizes, int n_in,
                              void* d_out, int out_size)
{
    // Bind inputs by element count (all four distinct) — robust to ordering.
    const int*   x      = nullptr;  int n_tokens = 0;
    const int4*  qw     = nullptr;
    const float* absmax = nullptr;
    const float* code   = nullptr;

    for (int i = 0; i < n_in; i++) {
        const int sz = in_sizes[i];
        if (sz == 256)            code   = (const float*)d_in[i];
        else if (sz == 12576)     absmax = (const float*)d_in[i];
        else if (sz > 1000000)    qw     = (const int4*)d_in[i];
        else                      { x = (const int*)d_in[i]; n_tokens = sz; }
    }

    float4* out = (float4*)d_out;
    const int n_groups = n_tokens / TOK;         // 4096
    const int grid = 148 * 4;                    // persistent, one wave at occ 4
    qembed_kernel<<<grid, 256>>>(x, qw, absmax, code, out, n_groups);
}

// round 7
// speedup vs baseline: 1.0590x; 1.0590x over previous
#include <cuda_runtime.h>
#include <cuda_bf16.h>
#include <cstdint>

// QuantizedEmbedding: out[i, d] = code[quant_weight[x[i], d]] * absmax[x[i] >> 2]
//   x: int32[16384]  qw: int32[50304,1024]  absmax: f32[12576]  code: f32[256]
//   out: f32[16384,1024]   (block index == v>>2 since (v%4)*1024 + d < 4096)
//
// R7: max-occupancy variant of R4. launch_bounds(256,8) -> <=32 regs,
// 64 warps/SM, 4 independent LDG.128 per thread in flight. x loaded as one
// broadcast int4. 4-way bank-interleaved 4KB codebook (R4 layout).

#define TOK_PER_CTA 4

__global__ void __launch_bounds__(256, 8)
qembed_kernel(const int4* __restrict__ x4,
              const int4* __restrict__ qw,
              const float* __restrict__ absmax,
              const float* __restrict__ code,
              float4* __restrict__ out)
{
    __shared__ float s_code[256 * 4];
    const int t = threadIdx.x;

    // One broadcast 16B load gives all 4 token ids for this CTA.
    const int4 v4 = x4[blockIdx.x];

    {
        const float cv = code[t];
        #pragma unroll
        for (int c = 0; c < 4; c++)
            s_code[t * 4 + c] = cv;
    }

    const int v[TOK_PER_CTA] = { v4.x, v4.y, v4.z, v4.w };

    // Front-batch 4 independent 16B row-chunk loads (MLP = 4/thread).
    int4 q[TOK_PER_CTA];
    #pragma unroll
    for (int k = 0; k < TOK_PER_CTA; k++)
        q[k] = qw[(size_t)v[k] * 256 + t];

    float scale[TOK_PER_CTA];
    #pragma unroll
    for (int k = 0; k < TOK_PER_CTA; k++)
        scale[k] = __ldg(&absmax[v[k] >> 2]);

    __syncthreads();

    const int c = t & 3;  // lane class -> disjoint bank set
    const size_t base = (size_t)blockIdx.x * (TOK_PER_CTA * 256) + t;
    #pragma unroll
    for (int k = 0; k < TOK_PER_CTA; k++) {
        float4 o;
        o.x = s_code[q[k].x * 4 + c] * scale[k];
        o.y = s_code[q[k].y * 4 + c] * scale[k];
        o.z = s_code[q[k].z * 4 + c] * scale[k];
        o.w = s_code[q[k].w * 4 + c] * scale[k];
        __stcs(&out[base + (size_t)k * 256], o);  // streaming store: keep qw in L2
    }
}

extern "C" void kernel_launch(void* const* d_in, const int* in_sizes, int n_in,
                              void* d_out, int out_size)
{
    // Bind inputs by element count (all four distinct) — robust to ordering.
    const int*   x      = nullptr;  int n_tokens = 0;
    const int4*  qw     = nullptr;
    const float* absmax = nullptr;
    const float* code   = nullptr;

    for (int i = 0; i < n_in; i++) {
        const int sz = in_sizes[i];
        if (sz == 256)            code   = (const float*)d_in[i];
        else if (sz == 12576)     absmax = (const float*)d_in[i];
        else if (sz > 1000000)    qw     = (const int4*)d_in[i];
        else                      { x = (const int*)d_in[i]; n_tokens = sz; }
    }

    float4* out = (float4*)d_out;
    const int n_cta = n_tokens / TOK_PER_CTA;  // 4096
    qembed_kernel<<<n_cta, 256>>>((const int4*)x, qw, absmax, code, out);
}